// round 1
// baseline (speedup 1.0000x reference)
#include <cuda_runtime.h>

// ---------------- problem constants ----------------
#define MTOT 65536      // B*T tokens
#define EF   256        // E features
#define HF   256        // H state size
#define LF   1024       // MLP hidden (pre-GLU)
#define NBLK 6
#define TLEN 2048
#define BB   32
#define NC   32         // scan chunks
#define TC   64         // chunk length (NC*TC == TLEN)

// ---------------- scratch (device globals; no allocation allowed) ----------------
static __device__ float g_y[(size_t)MTOT * EF];      // encoder output / residual anchor
static __device__ float g_x[(size_t)MTOT * EF];      // current block output
static __device__ float g_bure[(size_t)MTOT * HF];
static __device__ float g_buim[(size_t)MTOT * HF];
static __device__ float g_hre[(size_t)MTOT * HF];
static __device__ float g_him[(size_t)MTOT * HF];
static __device__ float g_u[(size_t)MTOT * EF];
static __device__ float g_g[(size_t)MTOT * (LF / 2)];
static __device__ float g_part[256 * 512];           // BN partial sums [256 blk][256 sum | 256 sumsq]
static __device__ float g_bna[EF];                   // BN fold: a = rsqrt(var+eps)*scale
static __device__ float g_bnc[EF];                   // BN fold: c = bias - mu*a
static __device__ float g_lr[HF], g_li[HF], g_gam[HF], g_L64r[HF], g_L64i[HF];
static __device__ float g_car_re[BB * NC * HF], g_car_im[BB * NC * HF];
static __device__ float g_pre_re[BB * NC * HF], g_pre_im[BB * NC * HF];
static __device__ float g_poolpart[BB * 8 * EF];
static __device__ float g_pool[BB * EF];

// ================= BN statistics (2-stage, deterministic) =================
__global__ void __launch_bounds__(256) bn_stage1(int xsel) {
    const float* x = xsel ? g_x : g_y;
    int blk = blockIdx.x;           // 256 blocks, 256 rows each
    int e = threadIdx.x;
    const float* p = x + (size_t)blk * 256 * EF + e;
    float s = 0.f, s2 = 0.f;
    for (int r = 0; r < 256; r++) {
        float v = p[(size_t)r * EF];
        s += v;
        s2 += v * v;
    }
    g_part[blk * 512 + e] = s;
    g_part[blk * 512 + 256 + e] = s2;
}

__global__ void __launch_bounds__(256) bn_stage2(const float* __restrict__ scale,
                                                 const float* __restrict__ bias) {
    int e = threadIdx.x;
    float s = 0.f, s2 = 0.f;
    for (int p = 0; p < 256; p++) {
        s += g_part[p * 512 + e];
        s2 += g_part[p * 512 + 256 + e];
    }
    const float inv = 1.0f / 65536.0f;
    float mu = s * inv;
    float var = fmaxf(s2 * inv - mu * mu, 0.0f);
    float a = rsqrtf(var + 1e-5f) * scale[e];
    g_bna[e] = a;
    g_bnc[e] = bias[e] - mu * a;
}

// ================= lambda / gamma precompute =================
__global__ void lam_kernel(const float* __restrict__ nul, const float* __restrict__ thl) {
    int h = threadIdx.x;
    float nu = expf(nul[h]);
    float th = expf(thl[h]);
    float r = expf(-nu);
    float sn, cs;
    sincosf(th, &sn, &cs);
    float lr = r * cs, li = r * sn;
    g_lr[h] = lr;
    g_li[h] = li;
    g_gam[h] = sqrtf(fmaxf(1.0f - r * r, 1e-12f));
    // lam^64 via 6 squarings
    float ar = lr, ai = li;
#pragma unroll
    for (int s = 0; s < 6; s++) {
        float nr = ar * ar - ai * ai;
        float ni = 2.0f * ar * ai;
        ar = nr;
        ai = ni;
    }
    g_L64r[h] = ar;
    g_L64i[h] = ai;
}

// ================= GEMM: Bu = BN(x) @ B^T * gamma  (TN, BN folded into A load) =================
// A: [M,256] row-major (raw x, BN applied on the fly). W: [256,256] row-major over K.
__global__ void __launch_bounds__(256) gemm_bu(int xsel, const float* __restrict__ W, int osel) {
    const float* A = xsel ? g_x : g_y;
    float* out = osel ? g_buim : g_bure;
    __shared__ __align__(16) float As[16][128];
    __shared__ __align__(16) float Bs[16][64];
    const int tid = threadIdx.x;
    const int m0 = blockIdx.x * 128;
    const int n0 = blockIdx.y * 64;
    const int tx = tid & 15;
    const int ty = tid >> 4;
    const int lr = tid >> 2;
    const int lk = (tid & 3) * 4;
    float acc[8][4];
#pragma unroll
    for (int j = 0; j < 8; j++)
#pragma unroll
        for (int i = 0; i < 4; i++) acc[j][i] = 0.f;

    for (int k0 = 0; k0 < 256; k0 += 16) {
        float4 a0 = *(const float4*)(A + (size_t)(m0 + lr) * 256 + k0 + lk);
        float4 a1 = *(const float4*)(A + (size_t)(m0 + lr + 64) * 256 + k0 + lk);
        float4 wv = *(const float4*)(W + (size_t)(n0 + lr) * 256 + k0 + lk);
        float4 ba = *(const float4*)(g_bna + k0 + lk);
        float4 bc = *(const float4*)(g_bnc + k0 + lk);
        a0.x = fmaf(ba.x, a0.x, bc.x); a0.y = fmaf(ba.y, a0.y, bc.y);
        a0.z = fmaf(ba.z, a0.z, bc.z); a0.w = fmaf(ba.w, a0.w, bc.w);
        a1.x = fmaf(ba.x, a1.x, bc.x); a1.y = fmaf(ba.y, a1.y, bc.y);
        a1.z = fmaf(ba.z, a1.z, bc.z); a1.w = fmaf(ba.w, a1.w, bc.w);
        __syncthreads();
        As[lk + 0][lr] = a0.x; As[lk + 1][lr] = a0.y; As[lk + 2][lr] = a0.z; As[lk + 3][lr] = a0.w;
        As[lk + 0][lr + 64] = a1.x; As[lk + 1][lr + 64] = a1.y;
        As[lk + 2][lr + 64] = a1.z; As[lk + 3][lr + 64] = a1.w;
        Bs[lk + 0][lr] = wv.x; Bs[lk + 1][lr] = wv.y; Bs[lk + 2][lr] = wv.z; Bs[lk + 3][lr] = wv.w;
        __syncthreads();
#pragma unroll
        for (int kk = 0; kk < 16; kk++) {
            float4 av0 = *(const float4*)&As[kk][ty * 8];
            float4 av1 = *(const float4*)&As[kk][ty * 8 + 4];
            float4 bv = *(const float4*)&Bs[kk][tx * 4];
            float a[8] = {av0.x, av0.y, av0.z, av0.w, av1.x, av1.y, av1.z, av1.w};
            float b[4] = {bv.x, bv.y, bv.z, bv.w};
#pragma unroll
            for (int j = 0; j < 8; j++)
#pragma unroll
                for (int i = 0; i < 4; i++) acc[j][i] = fmaf(a[j], b[i], acc[j][i]);
        }
    }
    float4 gm = *(const float4*)(g_gam + n0 + tx * 4);
#pragma unroll
    for (int j = 0; j < 8; j++) {
        float4 o;
        o.x = acc[j][0] * gm.x; o.y = acc[j][1] * gm.y;
        o.z = acc[j][2] * gm.z; o.w = acc[j][3] * gm.w;
        *(float4*)(out + (size_t)(m0 + ty * 8 + j) * 256 + n0 + tx * 4) = o;
    }
}

// ================= chunked scan =================
// pass A: per-(b,chunk,h) local scan from 0 -> carry
__global__ void __launch_bounds__(256) scan_carry() {
    int h = threadIdx.x;
    int c = blockIdx.x & 31;
    int b = blockIdx.x >> 5;
    float lr = g_lr[h], li = g_li[h];
    float hr = 0.f, hi = 0.f;
    size_t base = ((size_t)b * TLEN + c * TC) * HF + h;
#pragma unroll 4
    for (int t = 0; t < TC; t++) {
        float ur = g_bure[base + (size_t)t * HF];
        float ui = g_buim[base + (size_t)t * HF];
        float nr = fmaf(lr, hr, fmaf(-li, hi, ur));
        float ni = fmaf(lr, hi, fmaf(li, hr, ui));
        hr = nr;
        hi = ni;
    }
    int ci = (b * NC + c) * HF + h;
    g_car_re[ci] = hr;
    g_car_im[ci] = hi;
}

// pass B: combine carries sequentially with lam^TC -> incoming prefix per chunk
__global__ void __launch_bounds__(256) scan_prefix() {
    int h = threadIdx.x;
    int b = blockIdx.x;
    float Lr = g_L64r[h], Li = g_L64i[h];
    float Hr = 0.f, Hi = 0.f;
    for (int c = 0; c < NC; c++) {
        int ci = (b * NC + c) * HF + h;
        g_pre_re[ci] = Hr;
        g_pre_im[ci] = Hi;
        float cr = g_car_re[ci], cim = g_car_im[ci];
        float nr = fmaf(Lr, Hr, fmaf(-Li, Hi, cr));
        float ni = fmaf(Lr, Hi, fmaf(Li, Hr, cim));
        Hr = nr;
        Hi = ni;
    }
}

// pass C: re-sweep each chunk seeded with its prefix, write hs
__global__ void __launch_bounds__(256) scan_final() {
    int h = threadIdx.x;
    int c = blockIdx.x & 31;
    int b = blockIdx.x >> 5;
    float lr = g_lr[h], li = g_li[h];
    int ci = (b * NC + c) * HF + h;
    float hr = g_pre_re[ci], hi = g_pre_im[ci];
    size_t base = ((size_t)b * TLEN + c * TC) * HF + h;
#pragma unroll 4
    for (int t = 0; t < TC; t++) {
        size_t idx = base + (size_t)t * HF;
        float ur = g_bure[idx];
        float ui = g_buim[idx];
        float nr = fmaf(lr, hr, fmaf(-li, hi, ur));
        float ni = fmaf(lr, hi, fmaf(li, hr, ui));
        hr = nr;
        hi = ni;
        g_hre[idx] = hr;
        g_him[idx] = hi;
    }
}

// ================= GEMM: u = Re(hs @ Cc) + D*BN(x)  (dual TN) =================
__global__ void __launch_bounds__(256) gemm_cproj(const float* __restrict__ Wr,
                                                  const float* __restrict__ Wi,
                                                  const float* __restrict__ Dv, int xsel) {
    const float* Xin = xsel ? g_x : g_y;
    __shared__ __align__(16) float Asr[16][128];
    __shared__ __align__(16) float Asi[16][128];
    __shared__ __align__(16) float Bsr[16][64];
    __shared__ __align__(16) float Bsi[16][64];
    const int tid = threadIdx.x;
    const int m0 = blockIdx.x * 128;
    const int n0 = blockIdx.y * 64;
    const int tx = tid & 15;
    const int ty = tid >> 4;
    const int lr = tid >> 2;
    const int lk = (tid & 3) * 4;
    float acc[8][4];
#pragma unroll
    for (int j = 0; j < 8; j++)
#pragma unroll
        for (int i = 0; i < 4; i++) acc[j][i] = 0.f;

    for (int k0 = 0; k0 < 256; k0 += 16) {
        float4 ar0 = *(const float4*)(g_hre + (size_t)(m0 + lr) * 256 + k0 + lk);
        float4 ar1 = *(const float4*)(g_hre + (size_t)(m0 + lr + 64) * 256 + k0 + lk);
        float4 ai0 = *(const float4*)(g_him + (size_t)(m0 + lr) * 256 + k0 + lk);
        float4 ai1 = *(const float4*)(g_him + (size_t)(m0 + lr + 64) * 256 + k0 + lk);
        float4 wr = *(const float4*)(Wr + (size_t)(n0 + lr) * 256 + k0 + lk);
        float4 wi = *(const float4*)(Wi + (size_t)(n0 + lr) * 256 + k0 + lk);
        __syncthreads();
        Asr[lk + 0][lr] = ar0.x; Asr[lk + 1][lr] = ar0.y; Asr[lk + 2][lr] = ar0.z; Asr[lk + 3][lr] = ar0.w;
        Asr[lk + 0][lr + 64] = ar1.x; Asr[lk + 1][lr + 64] = ar1.y;
        Asr[lk + 2][lr + 64] = ar1.z; Asr[lk + 3][lr + 64] = ar1.w;
        Asi[lk + 0][lr] = ai0.x; Asi[lk + 1][lr] = ai0.y; Asi[lk + 2][lr] = ai0.z; Asi[lk + 3][lr] = ai0.w;
        Asi[lk + 0][lr + 64] = ai1.x; Asi[lk + 1][lr + 64] = ai1.y;
        Asi[lk + 2][lr + 64] = ai1.z; Asi[lk + 3][lr + 64] = ai1.w;
        Bsr[lk + 0][lr] = wr.x; Bsr[lk + 1][lr] = wr.y; Bsr[lk + 2][lr] = wr.z; Bsr[lk + 3][lr] = wr.w;
        Bsi[lk + 0][lr] = wi.x; Bsi[lk + 1][lr] = wi.y; Bsi[lk + 2][lr] = wi.z; Bsi[lk + 3][lr] = wi.w;
        __syncthreads();
#pragma unroll
        for (int kk = 0; kk < 16; kk++) {
            float4 r0 = *(const float4*)&Asr[kk][ty * 8];
            float4 r1 = *(const float4*)&Asr[kk][ty * 8 + 4];
            float4 i0 = *(const float4*)&Asi[kk][ty * 8];
            float4 i1 = *(const float4*)&Asi[kk][ty * 8 + 4];
            float4 br = *(const float4*)&Bsr[kk][tx * 4];
            float4 bi = *(const float4*)&Bsi[kk][tx * 4];
            float arv[8] = {r0.x, r0.y, r0.z, r0.w, r1.x, r1.y, r1.z, r1.w};
            float aiv[8] = {i0.x, i0.y, i0.z, i0.w, i1.x, i1.y, i1.z, i1.w};
            float brv[4] = {br.x, br.y, br.z, br.w};
            float biv[4] = {bi.x, bi.y, bi.z, bi.w};
#pragma unroll
            for (int j = 0; j < 8; j++)
#pragma unroll
                for (int i = 0; i < 4; i++) {
                    acc[j][i] = fmaf(arv[j], brv[i], acc[j][i]);
                    acc[j][i] = fmaf(-aiv[j], biv[i], acc[j][i]);
                }
        }
    }
    float4 dq = *(const float4*)(Dv + n0 + tx * 4);
    float4 ba = *(const float4*)(g_bna + n0 + tx * 4);
    float4 bc = *(const float4*)(g_bnc + n0 + tx * 4);
#pragma unroll
    for (int j = 0; j < 8; j++) {
        size_t row = (size_t)(m0 + ty * 8 + j);
        float4 xv = *(const float4*)(Xin + row * 256 + n0 + tx * 4);
        float4 o;
        o.x = acc[j][0] + dq.x * fmaf(ba.x, xv.x, bc.x);
        o.y = acc[j][1] + dq.y * fmaf(ba.y, xv.y, bc.y);
        o.z = acc[j][2] + dq.z * fmaf(ba.z, xv.z, bc.z);
        o.w = acc[j][3] + dq.w * fmaf(ba.w, xv.w, bc.w);
        *(float4*)(g_u + row * 256 + n0 + tx * 4) = o;
    }
}

// ================= GEMM: g = GLU(u @ W1 + b1)   (NN, dual-B tile) =================
__global__ void __launch_bounds__(256) gemm_glu(const float* __restrict__ W1,
                                                const float* __restrict__ b1) {
    __shared__ __align__(16) float As[16][128];
    __shared__ __align__(16) float Ba[16][64];
    __shared__ __align__(16) float Bb[16][64];
    const int tid = threadIdx.x;
    const int m0 = blockIdx.x * 128;
    const int n0 = blockIdx.y * 64;  // 0..448 (within 512)
    const int tx = tid & 15;
    const int ty = tid >> 4;
    const int lr = tid >> 2;
    const int lk = (tid & 3) * 4;
    const int bk = tid >> 4;
    const int bn = (tid & 15) * 4;
    float acca[8][4], accb[8][4];
#pragma unroll
    for (int j = 0; j < 8; j++)
#pragma unroll
        for (int i = 0; i < 4; i++) { acca[j][i] = 0.f; accb[j][i] = 0.f; }

    for (int k0 = 0; k0 < 256; k0 += 16) {
        float4 a0 = *(const float4*)(g_u + (size_t)(m0 + lr) * 256 + k0 + lk);
        float4 a1 = *(const float4*)(g_u + (size_t)(m0 + lr + 64) * 256 + k0 + lk);
        float4 wa = *(const float4*)(W1 + (size_t)(k0 + bk) * 1024 + n0 + bn);
        float4 wb = *(const float4*)(W1 + (size_t)(k0 + bk) * 1024 + 512 + n0 + bn);
        __syncthreads();
        As[lk + 0][lr] = a0.x; As[lk + 1][lr] = a0.y; As[lk + 2][lr] = a0.z; As[lk + 3][lr] = a0.w;
        As[lk + 0][lr + 64] = a1.x; As[lk + 1][lr + 64] = a1.y;
        As[lk + 2][lr + 64] = a1.z; As[lk + 3][lr + 64] = a1.w;
        *(float4*)&Ba[bk][bn] = wa;
        *(float4*)&Bb[bk][bn] = wb;
        __syncthreads();
#pragma unroll
        for (int kk = 0; kk < 16; kk++) {
            float4 av0 = *(const float4*)&As[kk][ty * 8];
            float4 av1 = *(const float4*)&As[kk][ty * 8 + 4];
            float4 bva = *(const float4*)&Ba[kk][tx * 4];
            float4 bvb = *(const float4*)&Bb[kk][tx * 4];
            float a[8] = {av0.x, av0.y, av0.z, av0.w, av1.x, av1.y, av1.z, av1.w};
            float ba_[4] = {bva.x, bva.y, bva.z, bva.w};
            float bb_[4] = {bvb.x, bvb.y, bvb.z, bvb.w};
#pragma unroll
            for (int j = 0; j < 8; j++)
#pragma unroll
                for (int i = 0; i < 4; i++) {
                    acca[j][i] = fmaf(a[j], ba_[i], acca[j][i]);
                    accb[j][i] = fmaf(a[j], bb_[i], accb[j][i]);
                }
        }
    }
    float4 b1a = *(const float4*)(b1 + n0 + tx * 4);
    float4 b1b = *(const float4*)(b1 + 512 + n0 + tx * 4);
#pragma unroll
    for (int j = 0; j < 8; j++) {
        float za[4], zb[4];
        za[0] = acca[j][0] + b1a.x; za[1] = acca[j][1] + b1a.y;
        za[2] = acca[j][2] + b1a.z; za[3] = acca[j][3] + b1a.w;
        zb[0] = accb[j][0] + b1b.x; zb[1] = accb[j][1] + b1b.y;
        zb[2] = accb[j][2] + b1b.z; zb[3] = accb[j][3] + b1b.w;
        float4 o;
        o.x = za[0] / (1.0f + expf(-zb[0]));
        o.y = za[1] / (1.0f + expf(-zb[1]));
        o.z = za[2] / (1.0f + expf(-zb[2]));
        o.w = za[3] / (1.0f + expf(-zb[3]));
        *(float4*)(g_g + (size_t)(m0 + ty * 8 + j) * 512 + n0 + tx * 4) = o;
    }
}

// ================= GEMM NN (encoder: ROLE=0, MLP2+residual: ROLE=1) =================
// ROLE 0: out(g_y) = A_ext[M,K] @ B[K,256] + bias          (K=64)
// ROLE 1: out(g_x) = g_g[M,512] @ B[512,256] + bias + g_y  (K=512)
template <int ROLE>
__global__ void __launch_bounds__(256) gemm_nn(const float* __restrict__ Aext, int K,
                                               const float* __restrict__ B,
                                               const float* __restrict__ bias) {
    const float* A = (ROLE == 0) ? Aext : g_g;
    float* out = (ROLE == 0) ? g_y : g_x;
    __shared__ __align__(16) float As[16][128];
    __shared__ __align__(16) float Bs[16][64];
    const int tid = threadIdx.x;
    const int m0 = blockIdx.x * 128;
    const int n0 = blockIdx.y * 64;
    const int tx = tid & 15;
    const int ty = tid >> 4;
    const int lr = tid >> 2;
    const int lk = (tid & 3) * 4;
    const int bk = tid >> 4;
    const int bn = (tid & 15) * 4;
    float acc[8][4];
#pragma unroll
    for (int j = 0; j < 8; j++)
#pragma unroll
        for (int i = 0; i < 4; i++) acc[j][i] = 0.f;

    for (int k0 = 0; k0 < K; k0 += 16) {
        float4 a0 = *(const float4*)(A + (size_t)(m0 + lr) * K + k0 + lk);
        float4 a1 = *(const float4*)(A + (size_t)(m0 + lr + 64) * K + k0 + lk);
        float4 wv = *(const float4*)(B + (size_t)(k0 + bk) * 256 + n0 + bn);
        __syncthreads();
        As[lk + 0][lr] = a0.x; As[lk + 1][lr] = a0.y; As[lk + 2][lr] = a0.z; As[lk + 3][lr] = a0.w;
        As[lk + 0][lr + 64] = a1.x; As[lk + 1][lr + 64] = a1.y;
        As[lk + 2][lr + 64] = a1.z; As[lk + 3][lr + 64] = a1.w;
        *(float4*)&Bs[bk][bn] = wv;
        __syncthreads();
#pragma unroll
        for (int kk = 0; kk < 16; kk++) {
            float4 av0 = *(const float4*)&As[kk][ty * 8];
            float4 av1 = *(const float4*)&As[kk][ty * 8 + 4];
            float4 bv = *(const float4*)&Bs[kk][tx * 4];
            float a[8] = {av0.x, av0.y, av0.z, av0.w, av1.x, av1.y, av1.z, av1.w};
            float b[4] = {bv.x, bv.y, bv.z, bv.w};
#pragma unroll
            for (int j = 0; j < 8; j++)
#pragma unroll
                for (int i = 0; i < 4; i++) acc[j][i] = fmaf(a[j], b[i], acc[j][i]);
        }
    }
    float4 bq = *(const float4*)(bias + n0 + tx * 4);
#pragma unroll
    for (int j = 0; j < 8; j++) {
        size_t row = (size_t)(m0 + ty * 8 + j);
        float4 o;
        o.x = acc[j][0] + bq.x; o.y = acc[j][1] + bq.y;
        o.z = acc[j][2] + bq.z; o.w = acc[j][3] + bq.w;
        if (ROLE == 1) {
            float4 yv = *(const float4*)(g_y + row * 256 + n0 + tx * 4);
            o.x += yv.x; o.y += yv.y; o.z += yv.z; o.w += yv.w;
        }
        *(float4*)(out + row * 256 + n0 + tx * 4) = o;
    }
}

// ================= mean pool + head =================
__global__ void __launch_bounds__(256) pool1() {
    int b = blockIdx.x >> 3;
    int c = blockIdx.x & 7;
    int e = threadIdx.x;
    const float* p = g_x + ((size_t)b * TLEN + c * 256) * EF + e;
    float s = 0.f;
#pragma unroll 8
    for (int t = 0; t < 256; t++) s += p[(size_t)t * EF];
    g_poolpart[(b * 8 + c) * EF + e] = s;
}

__global__ void __launch_bounds__(256) pool2() {
    int b = blockIdx.x;
    int e = threadIdx.x;
    float s = 0.f;
    for (int c = 0; c < 8; c++) s += g_poolpart[(b * 8 + c) * EF + e];
    g_pool[b * EF + e] = s * (1.0f / (float)TLEN);
}

__global__ void head(const float* __restrict__ Wout, const float* __restrict__ bout,
                     float* __restrict__ out) {
    int tid = threadIdx.x;
    if (tid >= 320) return;
    int b = tid / 10;
    int o = tid % 10;
    float s = bout[o];
    const float* p = g_pool + b * EF;
    for (int e = 0; e < 256; e++) s = fmaf(p[e], Wout[e * 10 + o], s);
    out[b * 10 + o] = s;
}

// ================= host orchestration =================
extern "C" void kernel_launch(void* const* d_in, const int* in_sizes, int n_in,
                              void* d_out, int out_size) {
    const float* x    = (const float*)d_in[0];   // [32,2048,64]
    const float* Wenc = (const float*)d_in[1];   // [64,256]
    const float* benc = (const float*)d_in[2];   // [256]
    const float* nul  = (const float*)d_in[3];   // [6,256]
    const float* thl  = (const float*)d_in[4];   // [6,256]
    const float* Bre  = (const float*)d_in[5];   // [6,256,256]
    const float* Bim  = (const float*)d_in[6];
    const float* Cre  = (const float*)d_in[7];   // [6,256,256]
    const float* Cim  = (const float*)d_in[8];
    const float* Dd   = (const float*)d_in[9];   // [6,256]
    const float* W1   = (const float*)d_in[10];  // [6,256,1024]
    const float* b1   = (const float*)d_in[11];  // [6,1024]
    const float* W2   = (const float*)d_in[12];  // [6,512,256]
    const float* b2   = (const float*)d_in[13];  // [6,256]
    const float* bns  = (const float*)d_in[14];  // [6,256]
    const float* bnb  = (const float*)d_in[15];  // [6,256]
    const float* Wout = (const float*)d_in[16];  // [256,10]
    const float* bout = (const float*)d_in[17];  // [10]

    dim3 g4(512, 4), g8(512, 8);

    // encoder: y = x @ W_enc + b_enc   (writes g_y)
    gemm_nn<0><<<g4, 256>>>(x, 64, Wenc, benc);

    int xsel = 0;  // 0 = read g_y, 1 = read g_x
    for (int i = 0; i < NBLK; i++) {
        bn_stage1<<<256, 256>>>(xsel);
        bn_stage2<<<1, 256>>>(bns + i * 256, bnb + i * 256);
        lam_kernel<<<1, 256>>>(nul + i * 256, thl + i * 256);
        gemm_bu<<<g4, 256>>>(xsel, Bre + (size_t)i * 65536, 0);
        gemm_bu<<<g4, 256>>>(xsel, Bim + (size_t)i * 65536, 1);
        scan_carry<<<BB * NC, 256>>>();
        scan_prefix<<<BB, 256>>>();
        scan_final<<<BB * NC, 256>>>();
        gemm_cproj<<<g4, 256>>>(Cre + (size_t)i * 65536, Cim + (size_t)i * 65536,
                                Dd + i * 256, xsel);
        gemm_glu<<<g8, 256>>>(W1 + (size_t)i * 256 * 1024, b1 + i * 1024);
        gemm_nn<1><<<g4, 256>>>(nullptr, 512, W2 + (size_t)i * 512 * 256, b2 + i * 256);
        xsel = 1;
    }
    pool1<<<BB * 8, 256>>>();
    pool2<<<BB, 256>>>();
    head<<<1, 320>>>(Wout, bout, (float*)d_out);
}